// round 15
// baseline (speedup 1.0000x reference)
#include <cuda_runtime.h>
#include <cuda_bf16.h>
#include <cstdint>
#include <math.h>

#define Bsz  64
#define Ssz  256
#define INP  400
#define Hsz  1024
#define H4   4096
#define Gsz  8192
#define NS   150
#define NR   50
#define NBLK 128

// ------------------------------- device scratch ---------------------------------
static __device__ float    d_Xg[(size_t)Ssz * Gsz * Bsz];   // [s][col(8192)][b]
static __device__ uint32_t d_Wp_hi[4194304];   // Whh A-frags [blk128][ks64][mw4][lane][4]
static __device__ uint32_t d_Wp_lo[4194304];
static __device__ uint32_t d_Tp_hi[32768];     // T B-frags [nw2][ks64][lane][8]
static __device__ uint32_t d_Tp_lo[32768];
static __device__ uint32_t d_WIp_hi[6553600];  // Wih A-frags [ct64][ks25][mw8][lane][4]
static __device__ uint32_t d_WIp_lo[6553600];
static __device__ uint32_t d_XIp_hi[3276800];  // x B-frags [s256][ks25][lane][16]
static __device__ uint32_t d_XIp_lo[3276800];
static __device__ uint32_t d_WAp_hi[114688];   // Wa A-frags [mt14][ks64][lane][4]
static __device__ uint32_t d_WAp_lo[114688];
static __device__ uint32_t d_HFp_hi[65536];    // h B-frags [cell2][nw2][ks64][lane][8]
static __device__ uint32_t d_HFp_lo[65536];
static __device__ float    d_lgG[8 * 200 * 64];  // logit K-partials [khB8][row200][batch64]
static __device__ unsigned g_bar, g_gen;

// ------------------------------- helpers -----------------------------------------
#define MMA16816(c, a0, a1, a2, a3, b0, b1) \
    asm volatile("mma.sync.aligned.m16n8k16.row.col.f32.bf16.bf16.f32 " \
        "{%0,%1,%2,%3}, {%4,%5,%6,%7}, {%8,%9}, {%0,%1,%2,%3};" \
        : "+f"((c)[0]), "+f"((c)[1]), "+f"((c)[2]), "+f"((c)[3]) \
        : "r"(a0), "r"(a1), "r"(a2), "r"(a3), "r"(b0), "r"(b1))

// R9's proven barrier: atomic arrivals + __threadfence (IVALL).
__device__ __forceinline__ void gridbar(unsigned& gen) {
    __syncthreads();
    if (threadIdx.x == 0) {
        __threadfence();
        if (atomicAdd(&g_bar, 1u) == NBLK - 1) {
            atomicExch(&g_bar, 0u);
            __threadfence();
            atomicAdd(&g_gen, 1u);
        } else {
            while (*(volatile unsigned*)&g_gen == gen) { }
        }
        __threadfence();   // acquire + L1 invalidate
    }
    __syncthreads();
    gen++;
}

__device__ __forceinline__ uint32_t pack_hi(float v0, float v1) {
    __nv_bfloat16 h0 = __float2bfloat16(v0), h1 = __float2bfloat16(v1);
    return (uint32_t)__bfloat16_as_ushort(h0) | ((uint32_t)__bfloat16_as_ushort(h1) << 16);
}
__device__ __forceinline__ uint32_t pack_lo(float v0, float v1) {
    __nv_bfloat16 h0 = __float2bfloat16(v0), h1 = __float2bfloat16(v1);
    float r0 = v0 - __bfloat162float(h0), r1 = v1 - __bfloat162float(h1);
    __nv_bfloat16 l0 = __float2bfloat16(r0), l1 = __float2bfloat16(r1);
    return (uint32_t)__bfloat16_as_ushort(l0) | ((uint32_t)__bfloat16_as_ushort(l1) << 16);
}
__device__ __forceinline__ float sigmf(float v) {
    return __fdividef(1.f, 1.f + __expf(-v));
}
__device__ __forceinline__ float tanhfast(float v) {
    return __fdividef(2.f, 1.f + __expf(-2.f * v)) - 1.f;
}

// =================================================================================
// pack Whh -> A-fragments
// =================================================================================
__global__ void __launch_bounds__(256) pack_whh_kernel(
    const float* __restrict__ WhhF, const float* __restrict__ WhhR)
{
    unsigned idx = blockIdx.x * 256u + threadIdx.x;        // < 4194304
    int w = idx & 3, lane = (idx >> 2) & 31, mw = (idx >> 7) & 3;
    int ks = (idx >> 9) & 63, blk = idx >> 15;
    int g = lane >> 2, t = lane & 3;
    int lr = g + 8 * (w & 1);
    int u = ((blk & 63) << 4) + lr;
    int k = ks * 16 + t * 2 + 8 * (w >> 1);
    const float* W = (blk >> 6) ? WhhR : WhhF;
    float2 v = *reinterpret_cast<const float2*>(&W[((size_t)mw * Hsz + u) * Hsz + k]);
    d_Wp_hi[idx] = pack_hi(v.x, v.y);
    d_Wp_lo[idx] = pack_lo(v.x, v.y);
}

// =================================================================================
// pack Wih (cat) -> A-fragments
// =================================================================================
__global__ void __launch_bounds__(256) pack_wih_kernel(
    const float* __restrict__ WihF, const float* __restrict__ WihR)
{
    unsigned idx = blockIdx.x * 256u + threadIdx.x;        // < 6553600
    int w = idx & 3, lane = (idx >> 2) & 31, mw = (idx >> 7) & 7;
    unsigned rest = idx >> 10;
    int ks = rest % 25, ct = rest / 25;
    int g = lane >> 2, t = lane & 3;
    int lr = g + 8 * (w & 1);
    int col = ct * 128 + mw * 16 + lr;
    int k = ks * 16 + t * 2 + 8 * (w >> 1);
    const float* W = (col < H4) ? (WihF + (size_t)col * INP)
                                : (WihR + (size_t)(col - H4) * INP);
    float2 v = *reinterpret_cast<const float2*>(&W[k]);
    d_WIp_hi[idx] = pack_hi(v.x, v.y);
    d_WIp_lo[idx] = pack_lo(v.x, v.y);
}

// =================================================================================
// pack x -> B-fragments
// =================================================================================
__global__ void __launch_bounds__(256) pack_x_kernel(const float* __restrict__ x)
{
    unsigned idx = blockIdx.x * 256u + threadIdx.x;        // < 3276800
    int w16 = idx & 15, lane = (idx >> 4) & 31;
    unsigned rest = idx >> 9;
    int ks = rest % 25, s = rest / 25;
    int nt = w16 >> 1, reg = w16 & 1;
    int b = nt * 8 + (lane >> 2);
    int k = ks * 16 + reg * 8 + (lane & 3) * 2;
    float2 v = *reinterpret_cast<const float2*>(&x[((size_t)b * Ssz + s) * INP + k]);
    d_XIp_hi[idx] = pack_hi(v.x, v.y);
    d_XIp_lo[idx] = pack_lo(v.x, v.y);
}

// =================================================================================
// pack Wa (F rows -> mtiles 0..9; R rows -> mtiles 10..13)
// =================================================================================
__global__ void __launch_bounds__(256) pack_wa_kernel(
    const float* __restrict__ WaFw, const float* __restrict__ WaRw)
{
    unsigned idx = blockIdx.x * 256u + threadIdx.x;        // < 114688
    int w = idx & 3, lane = (idx >> 2) & 31, ks = (idx >> 7) & 63, mt = idx >> 13;
    int g = lane >> 2, t = lane & 3;
    int lr = g + 8 * (w & 1);
    int k = ks * 16 + t * 2 + 8 * (w >> 1);
    float2 v = make_float2(0.f, 0.f);
    if (mt < 10) {
        int r = mt * 16 + lr;
        if (r < NS) v = *reinterpret_cast<const float2*>(&WaFw[(size_t)r * Hsz + k]);
    } else {
        int r = (mt - 10) * 16 + lr;
        if (r < NR) v = *reinterpret_cast<const float2*>(&WaRw[(size_t)r * Hsz + k]);
    }
    d_WAp_hi[idx] = pack_hi(v.x, v.y);
    d_WAp_lo[idx] = pack_lo(v.x, v.y);
}

// =================================================================================
// Phase A via HMMA bf16x3 (proven)
// =================================================================================
__global__ void __launch_bounds__(256, 2) phaseA_mma_kernel(
    const float* __restrict__ bihF, const float* __restrict__ bhhF,
    const float* __restrict__ bihR, const float* __restrict__ bhhR)
{
    const int s = blockIdx.x, ct = blockIdx.y;
    const int tid = threadIdx.x, wid = tid >> 5, lane = tid & 31;
    const int g = lane >> 2, t = lane & 3;

    float acc[8][4];
#pragma unroll
    for (int n = 0; n < 8; ++n)
#pragma unroll
        for (int i = 0; i < 4; ++i) acc[n][i] = 0.f;

    const uint4* pAh = (const uint4*)d_WIp_hi + ((size_t)(ct * 25) * 8 + wid) * 32 + lane;
    const uint4* pAl = (const uint4*)d_WIp_lo + ((size_t)(ct * 25) * 8 + wid) * 32 + lane;
    const uint4* pBh = (const uint4*)d_XIp_hi + ((size_t)(s * 25) * 32 + lane) * 4;
    const uint4* pBl = (const uint4*)d_XIp_lo + ((size_t)(s * 25) * 32 + lane) * 4;

    for (int ks = 0; ks < 25; ++ks) {
        uint32_t ah[4], al[4], bh[16], bl[16];
        *(uint4*)&ah[0] = __ldg(pAh);
        *(uint4*)&al[0] = __ldg(pAl);
#pragma unroll
        for (int j = 0; j < 4; ++j) {
            *(uint4*)&bh[4 * j] = __ldg(pBh + j);
            *(uint4*)&bl[4 * j] = __ldg(pBl + j);
        }
        pAh += 256; pAl += 256; pBh += 128; pBl += 128;
#pragma unroll
        for (int nt = 0; nt < 8; ++nt)
            MMA16816(acc[nt], ah[0], ah[1], ah[2], ah[3], bh[nt * 2], bh[nt * 2 + 1]);
#pragma unroll
        for (int nt = 0; nt < 8; ++nt)
            MMA16816(acc[nt], ah[0], ah[1], ah[2], ah[3], bl[nt * 2], bl[nt * 2 + 1]);
#pragma unroll
        for (int nt = 0; nt < 8; ++nt)
            MMA16816(acc[nt], al[0], al[1], al[2], al[3], bh[nt * 2], bh[nt * 2 + 1]);
    }

    const int cg0 = ct * 128 + wid * 16 + g, cg1 = cg0 + 8;
    float bs0 = (cg0 < H4) ? (bihF[cg0] + bhhF[cg0]) : (bihR[cg0 - H4] + bhhR[cg0 - H4]);
    float bs1 = (cg1 < H4) ? (bihF[cg1] + bhhF[cg1]) : (bihR[cg1 - H4] + bhhR[cg1 - H4]);
    float* base0 = &d_Xg[((size_t)s * Gsz + cg0) * Bsz];
    float* base1 = &d_Xg[((size_t)s * Gsz + cg1) * Bsz];
#pragma unroll
    for (int nt = 0; nt < 8; ++nt) {
        int n0 = nt * 8 + t * 2;
        *(float2*)&base0[n0] = make_float2(acc[nt][0] + bs0, acc[nt][1] + bs0);
        *(float2*)&base1[n0] = make_float2(acc[nt][2] + bs1, acc[nt][3] + bs1);
    }
}

// =================================================================================
// Phase B: exact R14 structure; changes: logits K-split 8-way over 112 blocks
// (4 serial iters each, phase 3 combines 8 partials) + items 4-acc chain break.
// =================================================================================
__global__ void __launch_bounds__(512, 1) phaseB_kernel(
    const float* __restrict__ WaFb, const float* __restrict__ WaRb,
    const float* __restrict__ Fw,   const float* __restrict__ Fb,
    const float* __restrict__ Rw,   const float* __restrict__ Rb,
    float* __restrict__ out)
{
    extern __shared__ uint4 smWlo[];   // 8192 uint4 = 128KB (this block's W_lo frags)

    const int tid = threadIdx.x, blk = blockIdx.x;
    const int cell = blk >> 6, u0 = (blk & 63) << 4;
    const int wid = tid >> 5, lane = tid & 31;
    const int mw = wid & 3, nw = (wid >> 2) & 1, kh = wid >> 3;
    const int g = lane >> 2, t = lane & 3;

    __shared__ float gsm[64][68];
    __shared__ float lgsm[16][68];
    __shared__ float lg[256];
    __shared__ float itm[64];
    __shared__ unsigned s_gen;

    for (int i = tid; i < 8192; i += 512)
        smWlo[i] = ((const uint4*)d_Wp_lo)[(size_t)blk * 8192 + i];

    {
        unsigned gi = blk * 512u + tid;
        if (gi < 32768u) { __stcg(&d_Tp_hi[gi], 0u); __stcg(&d_Tp_lo[gi], 0u); }
    }
    if (tid == 0) s_gen = atomicAdd(&g_gen, 0u);
    __syncthreads();
    unsigned gen = s_gen;
    gridbar(gen);

    const uint4* pAh0 = (const uint4*)d_Wp_hi + (size_t)blk * 8192 + kh * 4096 + mw * 32 + lane;
    const uint4* pBh0 = (const uint4*)d_Tp_hi + nw * 4096 + kh * 2048 + lane * 2;
    const uint4* pBl0 = (const uint4*)d_Tp_lo + nw * 4096 + kh * 2048 + lane * 2;
    const uint4* sWl0 = smWlo + kh * 4096 + mw * 32 + lane;

    const int gu = tid & 15, bq = tid >> 4;
    float cst[2] = {0.f, 0.f};

    float* outAF = out + (size_t)Bsz * Ssz * Hsz;
    float* outAR = outAF + (size_t)Bsz * Ssz * NS;

    for (int s = 0; s < Ssz; ++s) {
        // ---- prefetch Xg gate slice ---------------------------------------------
        float2 xg[4];
#pragma unroll
        for (int gate = 0; gate < 4; ++gate) {
            size_t col = (size_t)cell * H4 + (size_t)gate * Hsz + u0 + gu;
            xg[gate] = *reinterpret_cast<const float2*>(
                &d_Xg[((size_t)s * Gsz + col) * Bsz + bq * 2]);
        }

        // ---- recurrent GEMM (bf16x3 HMMA, W_lo from smem, plain-load T frags) ---
        float acc[4][4];
#pragma unroll
        for (int n = 0; n < 4; ++n)
#pragma unroll
            for (int i = 0; i < 4; ++i) acc[n][i] = 0.f;

        const uint4* pAh = pAh0; const uint4* pBh = pBh0; const uint4* pBl = pBl0;
        uint4 cAh = __ldg(pAh);
        uint4 cB0 = pBh[0], cB1 = pBh[1];
        uint4 cB2 = pBl[0], cB3 = pBl[1];

#pragma unroll 4
        for (int ks = 0; ks < 32; ++ks) {
            uint4 nAh, nB0, nB1, nB2, nB3;
            if (ks < 31) {
                pAh += 128; pBh += 64; pBl += 64;
                nAh = __ldg(pAh);
                nB0 = pBh[0]; nB1 = pBh[1];
                nB2 = pBl[0]; nB3 = pBl[1];
            }
            uint4 cAl = sWl0[ks * 128];
            MMA16816(acc[0], cAh.x, cAh.y, cAh.z, cAh.w, cB0.x, cB0.y);
            MMA16816(acc[1], cAh.x, cAh.y, cAh.z, cAh.w, cB0.z, cB0.w);
            MMA16816(acc[2], cAh.x, cAh.y, cAh.z, cAh.w, cB1.x, cB1.y);
            MMA16816(acc[3], cAh.x, cAh.y, cAh.z, cAh.w, cB1.z, cB1.w);
            MMA16816(acc[0], cAh.x, cAh.y, cAh.z, cAh.w, cB2.x, cB2.y);
            MMA16816(acc[1], cAh.x, cAh.y, cAh.z, cAh.w, cB2.z, cB2.w);
            MMA16816(acc[2], cAh.x, cAh.y, cAh.z, cAh.w, cB3.x, cB3.y);
            MMA16816(acc[3], cAh.x, cAh.y, cAh.z, cAh.w, cB3.z, cB3.w);
            MMA16816(acc[0], cAl.x, cAl.y, cAl.z, cAl.w, cB0.x, cB0.y);
            MMA16816(acc[1], cAl.x, cAl.y, cAl.z, cAl.w, cB0.z, cB0.w);
            MMA16816(acc[2], cAl.x, cAl.y, cAl.z, cAl.w, cB1.x, cB1.y);
            MMA16816(acc[3], cAl.x, cAl.y, cAl.z, cAl.w, cB1.z, cB1.w);
            cAh = nAh; cB0 = nB0; cB1 = nB1; cB2 = nB2; cB3 = nB3;
        }

        if (kh == 1) {
#pragma unroll
            for (int nt = 0; nt < 4; ++nt) {
                int col = nw * 32 + nt * 8 + t * 2;
                float* r0 = &gsm[mw * 16 + g][col];
                r0[0] = acc[nt][0]; r0[1] = acc[nt][1];
                float* r1 = &gsm[mw * 16 + g + 8][col];
                r1[0] = acc[nt][2]; r1[1] = acc[nt][3];
            }
        }
        __syncthreads();
        if (kh == 0) {
#pragma unroll
            for (int nt = 0; nt < 4; ++nt) {
                int col = nw * 32 + nt * 8 + t * 2;
                float* r0 = &gsm[mw * 16 + g][col];
                r0[0] += acc[nt][0]; r0[1] += acc[nt][1];
                float* r1 = &gsm[mw * 16 + g + 8][col];
                r1[0] += acc[nt][2]; r1[1] += acc[nt][3];
            }
        }
        __syncthreads();

        // ---- gates -> h, packed directly as B-fragments -------------------------
        {
            float hv[2];
#pragma unroll
            for (int i = 0; i < 2; ++i) {
                int b = bq * 2 + i;
                float iv = gsm[      gu][b] + (i ? xg[0].y : xg[0].x);
                float fv = gsm[16 + gu][b] + (i ? xg[1].y : xg[1].x);
                float gv = gsm[32 + gu][b] + (i ? xg[2].y : xg[2].x);
                float ov = gsm[48 + gu][b] + (i ? xg[3].y : xg[3].x);
                float c2 = sigmf(fv) * cst[i] + sigmf(iv) * tanhfast(gv);
                cst[i] = c2;
                hv[i] = sigmf(ov) * tanhfast(c2);
            }
            float q0 = __shfl_xor_sync(0xffffffffu, hv[0], 1);
            float q1 = __shfl_xor_sync(0xffffffffu, hv[1], 1);
            if (!(gu & 1)) {
                int k = u0 + gu;
                int ks = k >> 4, reg = (k >> 3) & 1, tq = (k >> 1) & 3;
#pragma unroll
                for (int e = 0; e < 2; ++e) {
                    int n = bq * 2 + e;
                    float va = e ? hv[1] : hv[0];
                    float vb = e ? q1 : q0;
                    int nw2 = n >> 5, nt3 = (n >> 3) & 3;
                    int lane_t = (n & 7) * 4 + tq;
                    size_t widx = ((((size_t)cell * 2 + nw2) * 64 + ks) * 32 + lane_t) * 8
                                  + nt3 * 2 + reg;
                    __stcg(&d_HFp_hi[widx], pack_hi(va, vb));
                    __stcg(&d_HFp_lo[widx], pack_lo(va, vb));
                }
            }
        }

        gridbar(gen);   // h fragments complete

        // ---- logits GEMM: 112 blocks, mt = blk>>3, khB = blk&7 (K eighths) ------
        if (blk < 112) {
            const int mt = blk >> 3, khB = blk & 7;
            const int cellL = (mt < 10) ? 0 : 1;
            const int ntL = wid & 7, khL = wid >> 3;
            float la[4] = {0.f, 0.f, 0.f, 0.f};
            const uint32_t* A_h = d_WAp_hi + (size_t)mt * 8192;
            const uint32_t* A_l = d_WAp_lo + (size_t)mt * 8192;
            const uint32_t* B_h = d_HFp_hi + ((size_t)(cellL * 2 + (ntL >> 2))) * 16384;
            const uint32_t* B_l = d_HFp_lo + ((size_t)(cellL * 2 + (ntL >> 2))) * 16384;
            const int boff = (ntL & 3) * 2;
            const int ksBeg = khB * 8 + khL * 4, ksEnd = ksBeg + 4;
            for (int ks = ksBeg; ks < ksEnd; ++ks) {
                uint4 ah = __ldg((const uint4*)(A_h + ((size_t)ks * 32 + lane) * 4));
                uint4 al = __ldg((const uint4*)(A_l + ((size_t)ks * 32 + lane) * 4));
                uint2 bh = __ldcg((const uint2*)(B_h + ((size_t)ks * 32 + lane) * 8 + boff));
                uint2 bl = __ldcg((const uint2*)(B_l + ((size_t)ks * 32 + lane) * 8 + boff));
                MMA16816(la, ah.x, ah.y, ah.z, ah.w, bh.x, bh.y);
                MMA16816(la, ah.x, ah.y, ah.z, ah.w, bl.x, bl.y);
                MMA16816(la, al.x, al.y, al.z, al.w, bh.x, bh.y);
            }
            if (khL == 1) {
                int col = ntL * 8 + t * 2;
                lgsm[g][col] = la[0];     lgsm[g][col + 1] = la[1];
                lgsm[g + 8][col] = la[2]; lgsm[g + 8][col + 1] = la[3];
            }
            __syncthreads();
            if (khL == 0) {
                int col = ntL * 8 + t * 2;
                lgsm[g][col] += la[0];     lgsm[g][col + 1] += la[1];
                lgsm[g + 8][col] += la[2]; lgsm[g + 8][col + 1] += la[3];
            }
            __syncthreads();
#pragma unroll
            for (int e = 0; e < 2; ++e) {
                int idx = tid * 2 + e;
                int rl = idx >> 6, n = idx & 63;
                int rlg = (mt < 10) ? mt * 16 + rl : (mt - 10) * 16 + rl;
                bool valid = (mt < 10) ? (rlg < NS) : (rlg < NR);
                if (valid) {
                    int rg = (mt < 10) ? rlg : NS + rlg;
                    __stcg(&d_lgG[khB * 12800 + rg * 64 + n], lgsm[rl][n]);
                }
            }
        }

        gridbar(gen);   // logits complete

        // ---- softmax + items + outer: block b (<64) handles batch b --------------
        if (blk < Bsz) {
            const int b = blk;
            if (tid < NS + NR) {
                float acc8 = (tid < NS) ? __ldg(&WaFb[tid]) : __ldg(&WaRb[tid - NS]);
#pragma unroll
                for (int p = 0; p < 8; ++p)
                    acc8 += __ldcg(&d_lgG[p * 12800 + tid * 64 + b]);
                lg[tid] = acc8;
            }
            __syncthreads();

            if (wid == 0) {
                float m = -1e30f;
                for (int n = lane; n < NS; n += 32) m = fmaxf(m, lg[n]);
#pragma unroll
                for (int off = 16; off; off >>= 1) m = fmaxf(m, __shfl_xor_sync(0xffffffffu, m, off));
                float ssum = 0.f;
                for (int n = lane; n < NS; n += 32) { float e = __expf(lg[n] - m); lg[n] = e; ssum += e; }
#pragma unroll
                for (int off = 16; off; off >>= 1) ssum += __shfl_xor_sync(0xffffffffu, ssum, off);
                float inv = 1.f / ssum;
                for (int n = lane; n < NS; n += 32) {
                    float a = lg[n] * inv; lg[n] = a;
                    outAF[((size_t)b * Ssz + s) * NS + n] = a;
                }
            } else if (wid == 1) {
                float m = -1e30f;
                for (int n = lane; n < NR; n += 32) m = fmaxf(m, lg[NS + n]);
#pragma unroll
                for (int off = 16; off; off >>= 1) m = fmaxf(m, __shfl_xor_sync(0xffffffffu, m, off));
                float ssum = 0.f;
                for (int n = lane; n < NR; n += 32) { float e = __expf(lg[NS + n] - m); lg[NS + n] = e; ssum += e; }
#pragma unroll
                for (int off = 16; off; off >>= 1) ssum += __shfl_xor_sync(0xffffffffu, ssum, off);
                float inv = 1.f / ssum;
                for (int n = lane; n < NR; n += 32) {
                    float a = lg[NS + n] * inv; lg[NS + n] = a;
                    outAR[((size_t)b * Ssz + s) * NR + n] = a;
                }
            }
            __syncthreads();

            // items: 4 independent accumulator chains (break serial FMA latency)
            if (tid < 32) {
                float s0 = 0.f, s1 = 0.f, s2 = 0.f, s3 = 0.f;
                const float* fw = &Fw[tid * NS];
                int n = 0;
                for (; n + 4 <= NS; n += 4) {
                    s0 = fmaf(lg[n],     __ldg(&fw[n]),     s0);
                    s1 = fmaf(lg[n + 1], __ldg(&fw[n + 1]), s1);
                    s2 = fmaf(lg[n + 2], __ldg(&fw[n + 2]), s2);
                    s3 = fmaf(lg[n + 3], __ldg(&fw[n + 3]), s3);
                }
                for (; n < NS; ++n) s0 = fmaf(lg[n], __ldg(&fw[n]), s0);
                itm[tid] = (s0 + s1) + (s2 + s3) + __ldg(&Fb[tid]);
            } else if (tid < 64) {
                int d = tid - 32;
                float s0 = 0.f, s1 = 0.f, s2 = 0.f, s3 = 0.f;
                const float* rw = &Rw[d * NR];
                int n = 0;
                for (; n + 4 <= NR; n += 4) {
                    s0 = fmaf(lg[NS + n],     __ldg(&rw[n]),     s0);
                    s1 = fmaf(lg[NS + n + 1], __ldg(&rw[n + 1]), s1);
                    s2 = fmaf(lg[NS + n + 2], __ldg(&rw[n + 2]), s2);
                    s3 = fmaf(lg[NS + n + 3], __ldg(&rw[n + 3]), s3);
                }
                for (; n < NR; ++n) s0 = fmaf(lg[NS + n], __ldg(&rw[n]), s0);
                itm[32 + d] = (s0 + s1) + (s2 + s3) + __ldg(&Rb[d]);
            }
            __syncthreads();

            // T row b -> main output + bf16 hi/lo B-fragments (512 words, 1/thread)
            {
                const int bnw = b >> 5, bnt = (b >> 3) & 3, bn = b & 7;
                int idx = tid;
                int ks = idx >> 3, q = idx & 3, reg = (idx >> 2) & 1;
                int k0 = ks * 16 + reg * 8 + q * 2;
                float v0 = itm[k0 >> 5] * itm[32 + (k0 & 31)];
                float v1 = itm[(k0 + 1) >> 5] * itm[32 + ((k0 + 1) & 31)];
                out[((size_t)b * Ssz + s) * Hsz + k0]     = v0;
                out[((size_t)b * Ssz + s) * Hsz + k0 + 1] = v1;
                int fl = bn * 4 + q;
                int word = ((bnw * 64 + ks) * 32 + fl) * 8 + bnt * 2 + reg;
                __stcg(&d_Tp_hi[word], pack_hi(v0, v1));
                __stcg(&d_Tp_lo[word], pack_lo(v0, v1));
            }
        }

        gridbar(gen);   // T fragments complete for next step
    }
}

// =================================================================================
extern "C" void kernel_launch(void* const* d_in, const int* in_sizes, int n_in,
                              void* d_out, int out_size) {
    (void)in_sizes; (void)n_in; (void)out_size;
    const float* x    = (const float*)d_in[0];
    const float* WihF = (const float*)d_in[1];
    const float* WhhF = (const float*)d_in[2];
    const float* bihF = (const float*)d_in[3];
    const float* bhhF = (const float*)d_in[4];
    const float* WihR = (const float*)d_in[5];
    const float* WhhR = (const float*)d_in[6];
    const float* bihR = (const float*)d_in[7];
    const float* bhhR = (const float*)d_in[8];
    const float* WaFw = (const float*)d_in[9];
    const float* WaFb = (const float*)d_in[10];
    const float* WaRw = (const float*)d_in[11];
    const float* WaRb = (const float*)d_in[12];
    const float* Fw   = (const float*)d_in[13];
    const float* Fb   = (const float*)d_in[14];
    const float* Rw   = (const float*)d_in[15];
    const float* Rb   = (const float*)d_in[16];
    float* out = (float*)d_out;

    cudaFuncSetAttribute(phaseB_kernel,
                         cudaFuncAttributeMaxDynamicSharedMemorySize, 131072);

    pack_whh_kernel<<<16384, 256>>>(WhhF, WhhR);
    pack_wih_kernel<<<25600, 256>>>(WihF, WihR);
    pack_x_kernel<<<12800, 256>>>(x);
    pack_wa_kernel<<<448, 256>>>(WaFw, WaRw);
    phaseA_mma_kernel<<<dim3(256, 64), 256>>>(bihF, bhhF, bihR, bhhR);
    phaseB_kernel<<<NBLK, 512, 131072>>>(WaFb, WaRb, Fw, Fb, Rw, Rb, out);
}

// round 16
// speedup vs baseline: 1.0363x; 1.0363x over previous
#include <cuda_runtime.h>
#include <cuda_bf16.h>
#include <cstdint>
#include <math.h>

#define Bsz  64
#define Ssz  256
#define INP  400
#define Hsz  1024
#define H4   4096
#define Gsz  8192
#define NS   150
#define NR   50
#define NBLK 128

// ------------------------------- device scratch ---------------------------------
static __device__ float    d_Xg[(size_t)Ssz * Gsz * Bsz];   // [s][col(8192)][b]
static __device__ uint32_t d_Wp_hi[4194304];   // Whh A-frags [blk128][ks64][mw4][lane][4]
static __device__ uint32_t d_Wp_lo[4194304];
static __device__ uint32_t d_Tp_hi[32768];     // T B-frags [nw2][ks64][lane][8]
static __device__ uint32_t d_Tp_lo[32768];
static __device__ uint32_t d_WIp_hi[6553600];  // Wih A-frags [ct64][ks25][mw8][lane][4]
static __device__ uint32_t d_WIp_lo[6553600];
static __device__ uint32_t d_XIp_hi[3276800];  // x B-frags [s256][ks25][lane][16]
static __device__ uint32_t d_XIp_lo[3276800];
static __device__ uint32_t d_WAp_hi[114688];   // Wa A-frags [mt14][ks64][lane][4]
static __device__ uint32_t d_WAp_lo[114688];
static __device__ uint32_t d_HFp_hi[65536];    // h B-frags [cell2][nw2][ks64][lane][8]
static __device__ uint32_t d_HFp_lo[65536];
static __device__ float    d_lgG[4 * 200 * 64];  // logit K-partials [khB4][row200][batch64]
static __device__ unsigned g_bar, g_gen, g_lgdone;

// ------------------------------- helpers -----------------------------------------
#define MMA16816(c, a0, a1, a2, a3, b0, b1) \
    asm volatile("mma.sync.aligned.m16n8k16.row.col.f32.bf16.bf16.f32 " \
        "{%0,%1,%2,%3}, {%4,%5,%6,%7}, {%8,%9}, {%0,%1,%2,%3};" \
        : "+f"((c)[0]), "+f"((c)[1]), "+f"((c)[2]), "+f"((c)[3]) \
        : "r"(a0), "r"(a1), "r"(a2), "r"(a3), "r"(b0), "r"(b1))

// R9's proven barrier: atomic arrivals + __threadfence (IVALL).
__device__ __forceinline__ void gridbar(unsigned& gen) {
    __syncthreads();
    if (threadIdx.x == 0) {
        __threadfence();
        if (atomicAdd(&g_bar, 1u) == NBLK - 1) {
            atomicExch(&g_bar, 0u);
            __threadfence();
            atomicAdd(&g_gen, 1u);
        } else {
            while (*(volatile unsigned*)&g_gen == gen) { }
        }
        __threadfence();   // acquire + L1 invalidate
    }
    __syncthreads();
    gen++;
}

__device__ __forceinline__ uint32_t pack_hi(float v0, float v1) {
    __nv_bfloat16 h0 = __float2bfloat16(v0), h1 = __float2bfloat16(v1);
    return (uint32_t)__bfloat16_as_ushort(h0) | ((uint32_t)__bfloat16_as_ushort(h1) << 16);
}
__device__ __forceinline__ uint32_t pack_lo(float v0, float v1) {
    __nv_bfloat16 h0 = __float2bfloat16(v0), h1 = __float2bfloat16(v1);
    float r0 = v0 - __bfloat162float(h0), r1 = v1 - __bfloat162float(h1);
    __nv_bfloat16 l0 = __float2bfloat16(r0), l1 = __float2bfloat16(r1);
    return (uint32_t)__bfloat16_as_ushort(l0) | ((uint32_t)__bfloat16_as_ushort(l1) << 16);
}
__device__ __forceinline__ float sigmf(float v) {
    return __fdividef(1.f, 1.f + __expf(-v));
}
__device__ __forceinline__ float tanhfast(float v) {
    return __fdividef(2.f, 1.f + __expf(-2.f * v)) - 1.f;
}

// =================================================================================
// pack Whh -> A-fragments
// =================================================================================
__global__ void __launch_bounds__(256) pack_whh_kernel(
    const float* __restrict__ WhhF, const float* __restrict__ WhhR)
{
    unsigned idx = blockIdx.x * 256u + threadIdx.x;        // < 4194304
    int w = idx & 3, lane = (idx >> 2) & 31, mw = (idx >> 7) & 3;
    int ks = (idx >> 9) & 63, blk = idx >> 15;
    int g = lane >> 2, t = lane & 3;
    int lr = g + 8 * (w & 1);
    int u = ((blk & 63) << 4) + lr;
    int k = ks * 16 + t * 2 + 8 * (w >> 1);
    const float* W = (blk >> 6) ? WhhR : WhhF;
    float2 v = *reinterpret_cast<const float2*>(&W[((size_t)mw * Hsz + u) * Hsz + k]);
    d_Wp_hi[idx] = pack_hi(v.x, v.y);
    d_Wp_lo[idx] = pack_lo(v.x, v.y);
}

// =================================================================================
// pack Wih (cat) -> A-fragments
// =================================================================================
__global__ void __launch_bounds__(256) pack_wih_kernel(
    const float* __restrict__ WihF, const float* __restrict__ WihR)
{
    unsigned idx = blockIdx.x * 256u + threadIdx.x;        // < 6553600
    int w = idx & 3, lane = (idx >> 2) & 31, mw = (idx >> 7) & 7;
    unsigned rest = idx >> 10;
    int ks = rest % 25, ct = rest / 25;
    int g = lane >> 2, t = lane & 3;
    int lr = g + 8 * (w & 1);
    int col = ct * 128 + mw * 16 + lr;
    int k = ks * 16 + t * 2 + 8 * (w >> 1);
    const float* W = (col < H4) ? (WihF + (size_t)col * INP)
                                : (WihR + (size_t)(col - H4) * INP);
    float2 v = *reinterpret_cast<const float2*>(&W[k]);
    d_WIp_hi[idx] = pack_hi(v.x, v.y);
    d_WIp_lo[idx] = pack_lo(v.x, v.y);
}

// =================================================================================
// pack x -> B-fragments
// =================================================================================
__global__ void __launch_bounds__(256) pack_x_kernel(const float* __restrict__ x)
{
    unsigned idx = blockIdx.x * 256u + threadIdx.x;        // < 3276800
    int w16 = idx & 15, lane = (idx >> 4) & 31;
    unsigned rest = idx >> 9;
    int ks = rest % 25, s = rest / 25;
    int nt = w16 >> 1, reg = w16 & 1;
    int b = nt * 8 + (lane >> 2);
    int k = ks * 16 + reg * 8 + (lane & 3) * 2;
    float2 v = *reinterpret_cast<const float2*>(&x[((size_t)b * Ssz + s) * INP + k]);
    d_XIp_hi[idx] = pack_hi(v.x, v.y);
    d_XIp_lo[idx] = pack_lo(v.x, v.y);
}

// =================================================================================
// pack Wa (F rows -> mtiles 0..9; R rows -> mtiles 10..13)
// =================================================================================
__global__ void __launch_bounds__(256) pack_wa_kernel(
    const float* __restrict__ WaFw, const float* __restrict__ WaRw)
{
    unsigned idx = blockIdx.x * 256u + threadIdx.x;        // < 114688
    int w = idx & 3, lane = (idx >> 2) & 31, ks = (idx >> 7) & 63, mt = idx >> 13;
    int g = lane >> 2, t = lane & 3;
    int lr = g + 8 * (w & 1);
    int k = ks * 16 + t * 2 + 8 * (w >> 1);
    float2 v = make_float2(0.f, 0.f);
    if (mt < 10) {
        int r = mt * 16 + lr;
        if (r < NS) v = *reinterpret_cast<const float2*>(&WaFw[(size_t)r * Hsz + k]);
    } else {
        int r = (mt - 10) * 16 + lr;
        if (r < NR) v = *reinterpret_cast<const float2*>(&WaRw[(size_t)r * Hsz + k]);
    }
    d_WAp_hi[idx] = pack_hi(v.x, v.y);
    d_WAp_lo[idx] = pack_lo(v.x, v.y);
}

// =================================================================================
// Phase A via HMMA bf16x3 (proven)
// =================================================================================
__global__ void __launch_bounds__(256, 2) phaseA_mma_kernel(
    const float* __restrict__ bihF, const float* __restrict__ bhhF,
    const float* __restrict__ bihR, const float* __restrict__ bhhR)
{
    const int s = blockIdx.x, ct = blockIdx.y;
    const int tid = threadIdx.x, wid = tid >> 5, lane = tid & 31;
    const int g = lane >> 2, t = lane & 3;

    float acc[8][4];
#pragma unroll
    for (int n = 0; n < 8; ++n)
#pragma unroll
        for (int i = 0; i < 4; ++i) acc[n][i] = 0.f;

    const uint4* pAh = (const uint4*)d_WIp_hi + ((size_t)(ct * 25) * 8 + wid) * 32 + lane;
    const uint4* pAl = (const uint4*)d_WIp_lo + ((size_t)(ct * 25) * 8 + wid) * 32 + lane;
    const uint4* pBh = (const uint4*)d_XIp_hi + ((size_t)(s * 25) * 32 + lane) * 4;
    const uint4* pBl = (const uint4*)d_XIp_lo + ((size_t)(s * 25) * 32 + lane) * 4;

    for (int ks = 0; ks < 25; ++ks) {
        uint32_t ah[4], al[4], bh[16], bl[16];
        *(uint4*)&ah[0] = __ldg(pAh);
        *(uint4*)&al[0] = __ldg(pAl);
#pragma unroll
        for (int j = 0; j < 4; ++j) {
            *(uint4*)&bh[4 * j] = __ldg(pBh + j);
            *(uint4*)&bl[4 * j] = __ldg(pBl + j);
        }
        pAh += 256; pAl += 256; pBh += 128; pBl += 128;
#pragma unroll
        for (int nt = 0; nt < 8; ++nt)
            MMA16816(acc[nt], ah[0], ah[1], ah[2], ah[3], bh[nt * 2], bh[nt * 2 + 1]);
#pragma unroll
        for (int nt = 0; nt < 8; ++nt)
            MMA16816(acc[nt], ah[0], ah[1], ah[2], ah[3], bl[nt * 2], bl[nt * 2 + 1]);
#pragma unroll
        for (int nt = 0; nt < 8; ++nt)
            MMA16816(acc[nt], al[0], al[1], al[2], al[3], bh[nt * 2], bh[nt * 2 + 1]);
    }

    const int cg0 = ct * 128 + wid * 16 + g, cg1 = cg0 + 8;
    float bs0 = (cg0 < H4) ? (bihF[cg0] + bhhF[cg0]) : (bihR[cg0 - H4] + bhhR[cg0 - H4]);
    float bs1 = (cg1 < H4) ? (bihF[cg1] + bhhF[cg1]) : (bihR[cg1 - H4] + bhhR[cg1 - H4]);
    float* base0 = &d_Xg[((size_t)s * Gsz + cg0) * Bsz];
    float* base1 = &d_Xg[((size_t)s * Gsz + cg1) * Bsz];
#pragma unroll
    for (int nt = 0; nt < 8; ++nt) {
        int n0 = nt * 8 + t * 2;
        *(float2*)&base0[n0] = make_float2(acc[nt][0] + bs0, acc[nt][1] + bs0);
        *(float2*)&base1[n0] = make_float2(acc[nt][2] + bs1, acc[nt][3] + bs1);
    }
}

// =================================================================================
// Phase B: exact R14 structure; ONLY change: barrier 2 replaced by a
// producer-counter sync (56 logits blocks signal; 64 attention blocks wait).
// =================================================================================
__global__ void __launch_bounds__(512, 1) phaseB_kernel(
    const float* __restrict__ WaFb, const float* __restrict__ WaRb,
    const float* __restrict__ Fw,   const float* __restrict__ Fb,
    const float* __restrict__ Rw,   const float* __restrict__ Rb,
    float* __restrict__ out)
{
    extern __shared__ uint4 smWlo[];   // 8192 uint4 = 128KB (this block's W_lo frags)

    const int tid = threadIdx.x, blk = blockIdx.x;
    const int cell = blk >> 6, u0 = (blk & 63) << 4;
    const int wid = tid >> 5, lane = tid & 31;
    const int mw = wid & 3, nw = (wid >> 2) & 1, kh = wid >> 3;
    const int g = lane >> 2, t = lane & 3;

    __shared__ float gsm[64][68];
    __shared__ float lgsm[16][68];
    __shared__ float lg[256];
    __shared__ float itm[64];
    __shared__ unsigned s_gen, s_lgbase;

    for (int i = tid; i < 8192; i += 512)
        smWlo[i] = ((const uint4*)d_Wp_lo)[(size_t)blk * 8192 + i];

    {
        unsigned gi = blk * 512u + tid;
        if (gi < 32768u) { __stcg(&d_Tp_hi[gi], 0u); __stcg(&d_Tp_lo[gi], 0u); }
    }
    if (tid == 0) {
        s_gen = atomicAdd(&g_gen, 0u);
        s_lgbase = atomicAdd(&g_lgdone, 0u);   // read before any signaling this launch
    }
    __syncthreads();
    unsigned gen = s_gen;
    const unsigned lgbase = s_lgbase;
    gridbar(gen);

    const uint4* pAh0 = (const uint4*)d_Wp_hi + (size_t)blk * 8192 + kh * 4096 + mw * 32 + lane;
    const uint4* pBh0 = (const uint4*)d_Tp_hi + nw * 4096 + kh * 2048 + lane * 2;
    const uint4* pBl0 = (const uint4*)d_Tp_lo + nw * 4096 + kh * 2048 + lane * 2;
    const uint4* sWl0 = smWlo + kh * 4096 + mw * 32 + lane;

    const int gu = tid & 15, bq = tid >> 4;
    float cst[2] = {0.f, 0.f};

    float* outAF = out + (size_t)Bsz * Ssz * Hsz;
    float* outAR = outAF + (size_t)Bsz * Ssz * NS;

    for (int s = 0; s < Ssz; ++s) {
        // ---- prefetch Xg gate slice ---------------------------------------------
        float2 xg[4];
#pragma unroll
        for (int gate = 0; gate < 4; ++gate) {
            size_t col = (size_t)cell * H4 + (size_t)gate * Hsz + u0 + gu;
            xg[gate] = *reinterpret_cast<const float2*>(
                &d_Xg[((size_t)s * Gsz + col) * Bsz + bq * 2]);
        }

        // ---- recurrent GEMM (bf16x3 HMMA, W_lo from smem, plain-load T frags) ---
        float acc[4][4];
#pragma unroll
        for (int n = 0; n < 4; ++n)
#pragma unroll
            for (int i = 0; i < 4; ++i) acc[n][i] = 0.f;

        const uint4* pAh = pAh0; const uint4* pBh = pBh0; const uint4* pBl = pBl0;
        uint4 cAh = __ldg(pAh);
        uint4 cB0 = pBh[0], cB1 = pBh[1];
        uint4 cB2 = pBl[0], cB3 = pBl[1];

#pragma unroll 4
        for (int ks = 0; ks < 32; ++ks) {
            uint4 nAh, nB0, nB1, nB2, nB3;
            if (ks < 31) {
                pAh += 128; pBh += 64; pBl += 64;
                nAh = __ldg(pAh);
                nB0 = pBh[0]; nB1 = pBh[1];
                nB2 = pBl[0]; nB3 = pBl[1];
            }
            uint4 cAl = sWl0[ks * 128];
            MMA16816(acc[0], cAh.x, cAh.y, cAh.z, cAh.w, cB0.x, cB0.y);
            MMA16816(acc[1], cAh.x, cAh.y, cAh.z, cAh.w, cB0.z, cB0.w);
            MMA16816(acc[2], cAh.x, cAh.y, cAh.z, cAh.w, cB1.x, cB1.y);
            MMA16816(acc[3], cAh.x, cAh.y, cAh.z, cAh.w, cB1.z, cB1.w);
            MMA16816(acc[0], cAh.x, cAh.y, cAh.z, cAh.w, cB2.x, cB2.y);
            MMA16816(acc[1], cAh.x, cAh.y, cAh.z, cAh.w, cB2.z, cB2.w);
            MMA16816(acc[2], cAh.x, cAh.y, cAh.z, cAh.w, cB3.x, cB3.y);
            MMA16816(acc[3], cAh.x, cAh.y, cAh.z, cAh.w, cB3.z, cB3.w);
            MMA16816(acc[0], cAl.x, cAl.y, cAl.z, cAl.w, cB0.x, cB0.y);
            MMA16816(acc[1], cAl.x, cAl.y, cAl.z, cAl.w, cB0.z, cB0.w);
            MMA16816(acc[2], cAl.x, cAl.y, cAl.z, cAl.w, cB1.x, cB1.y);
            MMA16816(acc[3], cAl.x, cAl.y, cAl.z, cAl.w, cB1.z, cB1.w);
            cAh = nAh; cB0 = nB0; cB1 = nB1; cB2 = nB2; cB3 = nB3;
        }

        if (kh == 1) {
#pragma unroll
            for (int nt = 0; nt < 4; ++nt) {
                int col = nw * 32 + nt * 8 + t * 2;
                float* r0 = &gsm[mw * 16 + g][col];
                r0[0] = acc[nt][0]; r0[1] = acc[nt][1];
                float* r1 = &gsm[mw * 16 + g + 8][col];
                r1[0] = acc[nt][2]; r1[1] = acc[nt][3];
            }
        }
        __syncthreads();
        if (kh == 0) {
#pragma unroll
            for (int nt = 0; nt < 4; ++nt) {
                int col = nw * 32 + nt * 8 + t * 2;
                float* r0 = &gsm[mw * 16 + g][col];
                r0[0] += acc[nt][0]; r0[1] += acc[nt][1];
                float* r1 = &gsm[mw * 16 + g + 8][col];
                r1[0] += acc[nt][2]; r1[1] += acc[nt][3];
            }
        }
        __syncthreads();

        // ---- gates -> h, packed directly as B-fragments -------------------------
        {
            float hv[2];
#pragma unroll
            for (int i = 0; i < 2; ++i) {
                int b = bq * 2 + i;
                float iv = gsm[      gu][b] + (i ? xg[0].y : xg[0].x);
                float fv = gsm[16 + gu][b] + (i ? xg[1].y : xg[1].x);
                float gv = gsm[32 + gu][b] + (i ? xg[2].y : xg[2].x);
                float ov = gsm[48 + gu][b] + (i ? xg[3].y : xg[3].x);
                float c2 = sigmf(fv) * cst[i] + sigmf(iv) * tanhfast(gv);
                cst[i] = c2;
                hv[i] = sigmf(ov) * tanhfast(c2);
            }
            float q0 = __shfl_xor_sync(0xffffffffu, hv[0], 1);
            float q1 = __shfl_xor_sync(0xffffffffu, hv[1], 1);
            if (!(gu & 1)) {
                int k = u0 + gu;
                int ks = k >> 4, reg = (k >> 3) & 1, tq = (k >> 1) & 3;
#pragma unroll
                for (int e = 0; e < 2; ++e) {
                    int n = bq * 2 + e;
                    float va = e ? hv[1] : hv[0];
                    float vb = e ? q1 : q0;
                    int nw2 = n >> 5, nt3 = (n >> 3) & 3;
                    int lane_t = (n & 7) * 4 + tq;
                    size_t widx = ((((size_t)cell * 2 + nw2) * 64 + ks) * 32 + lane_t) * 8
                                  + nt3 * 2 + reg;
                    __stcg(&d_HFp_hi[widx], pack_hi(va, vb));
                    __stcg(&d_HFp_lo[widx], pack_lo(va, vb));
                }
            }
        }

        gridbar(gen);   // h fragments complete (barrier 1)

        // ---- logits GEMM: 56 blocks, mt = blk>>2, khB = blk&3 (K quarters) ------
        if (blk < 56) {
            const int mt = blk >> 2, khB = blk & 3;
            const int cellL = (mt < 10) ? 0 : 1;
            const int ntL = wid & 7, khL = wid >> 3;
            float la[4] = {0.f, 0.f, 0.f, 0.f};
            const uint32_t* A_h = d_WAp_hi + (size_t)mt * 8192;
            const uint32_t* A_l = d_WAp_lo + (size_t)mt * 8192;
            const uint32_t* B_h = d_HFp_hi + ((size_t)(cellL * 2 + (ntL >> 2))) * 16384;
            const uint32_t* B_l = d_HFp_lo + ((size_t)(cellL * 2 + (ntL >> 2))) * 16384;
            const int boff = (ntL & 3) * 2;
            const int ksBeg = khB * 16 + khL * 8, ksEnd = ksBeg + 8;
            for (int ks = ksBeg; ks < ksEnd; ++ks) {
                uint4 ah = __ldg((const uint4*)(A_h + ((size_t)ks * 32 + lane) * 4));
                uint4 al = __ldg((const uint4*)(A_l + ((size_t)ks * 32 + lane) * 4));
                uint2 bh = __ldcg((const uint2*)(B_h + ((size_t)ks * 32 + lane) * 8 + boff));
                uint2 bl = __ldcg((const uint2*)(B_l + ((size_t)ks * 32 + lane) * 8 + boff));
                MMA16816(la, ah.x, ah.y, ah.z, ah.w, bh.x, bh.y);
                MMA16816(la, ah.x, ah.y, ah.z, ah.w, bl.x, bl.y);
                MMA16816(la, al.x, al.y, al.z, al.w, bh.x, bh.y);
            }
            if (khL == 1) {
                int col = ntL * 8 + t * 2;
                lgsm[g][col] = la[0];     lgsm[g][col + 1] = la[1];
                lgsm[g + 8][col] = la[2]; lgsm[g + 8][col + 1] = la[3];
            }
            __syncthreads();
            if (khL == 0) {
                int col = ntL * 8 + t * 2;
                lgsm[g][col] += la[0];     lgsm[g][col + 1] += la[1];
                lgsm[g + 8][col] += la[2]; lgsm[g + 8][col + 1] += la[3];
            }
            __syncthreads();
#pragma unroll
            for (int e = 0; e < 2; ++e) {
                int idx = tid * 2 + e;
                int rl = idx >> 6, n = idx & 63;
                int rlg = (mt < 10) ? mt * 16 + rl : (mt - 10) * 16 + rl;
                bool valid = (mt < 10) ? (rlg < NS) : (rlg < NR);
                if (valid) {
                    int rg = (mt < 10) ? rlg : NS + rlg;
                    __stcg(&d_lgG[khB * 12800 + rg * 64 + n], lgsm[rl][n]);
                }
            }
            // signal: this producer's logit partials are visible
            __syncthreads();
            if (tid == 0) {
                __threadfence();
                atomicAdd(&g_lgdone, 1u);
            }
        }

        // ---- consumers wait for all 56 logits producers (partial sync) ----------
        if (blk < Bsz) {
            if (tid == 0) {
                const unsigned tgt = lgbase + 56u * (unsigned)(s + 1);
                while (*(volatile unsigned*)&g_lgdone < tgt) { }
                __threadfence();   // acquire
            }
            __syncthreads();

            const int b = blk;
            if (tid < NS + NR)
                lg[tid] = __ldcg(&d_lgG[tid * 64 + b])
                          + __ldcg(&d_lgG[12800 + tid * 64 + b])
                          + __ldcg(&d_lgG[25600 + tid * 64 + b])
                          + __ldcg(&d_lgG[38400 + tid * 64 + b])
                          + ((tid < NS) ? __ldg(&WaFb[tid]) : __ldg(&WaRb[tid - NS]));
            __syncthreads();

            if (wid == 0) {
                float m = -1e30f;
                for (int n = lane; n < NS; n += 32) m = fmaxf(m, lg[n]);
#pragma unroll
                for (int off = 16; off; off >>= 1) m = fmaxf(m, __shfl_xor_sync(0xffffffffu, m, off));
                float ssum = 0.f;
                for (int n = lane; n < NS; n += 32) { float e = __expf(lg[n] - m); lg[n] = e; ssum += e; }
#pragma unroll
                for (int off = 16; off; off >>= 1) ssum += __shfl_xor_sync(0xffffffffu, ssum, off);
                float inv = 1.f / ssum;
                for (int n = lane; n < NS; n += 32) {
                    float a = lg[n] * inv; lg[n] = a;
                    outAF[((size_t)b * Ssz + s) * NS + n] = a;
                }
            } else if (wid == 1) {
                float m = -1e30f;
                for (int n = lane; n < NR; n += 32) m = fmaxf(m, lg[NS + n]);
#pragma unroll
                for (int off = 16; off; off >>= 1) m = fmaxf(m, __shfl_xor_sync(0xffffffffu, m, off));
                float ssum = 0.f;
                for (int n = lane; n < NR; n += 32) { float e = __expf(lg[NS + n] - m); lg[NS + n] = e; ssum += e; }
#pragma unroll
                for (int off = 16; off; off >>= 1) ssum += __shfl_xor_sync(0xffffffffu, ssum, off);
                float inv = 1.f / ssum;
                for (int n = lane; n < NR; n += 32) {
                    float a = lg[NS + n] * inv; lg[NS + n] = a;
                    outAR[((size_t)b * Ssz + s) * NR + n] = a;
                }
            }
            __syncthreads();

            if (tid < 32) {
                float sum = Fb[tid];
                for (int n = 0; n < NS; ++n) sum = fmaf(lg[n], __ldg(&Fw[tid * NS + n]), sum);
                itm[tid] = sum;
            } else if (tid < 64) {
                int d = tid - 32;
                float sum = Rb[d];
                for (int n = 0; n < NR; ++n) sum = fmaf(lg[NS + n], __ldg(&Rw[d * NR + n]), sum);
                itm[32 + d] = sum;
            }
            __syncthreads();

            // T row b -> main output + bf16 hi/lo B-fragments (512 words, 1/thread)
            {
                const int bnw = b >> 5, bnt = (b >> 3) & 3, bn = b & 7;
                int idx = tid;
                int ks = idx >> 3, q = idx & 3, reg = (idx >> 2) & 1;
                int k0 = ks * 16 + reg * 8 + q * 2;
                float v0 = itm[k0 >> 5] * itm[32 + (k0 & 31)];
                float v1 = itm[(k0 + 1) >> 5] * itm[32 + ((k0 + 1) & 31)];
                out[((size_t)b * Ssz + s) * Hsz + k0]     = v0;
                out[((size_t)b * Ssz + s) * Hsz + k0 + 1] = v1;
                int fl = bn * 4 + q;
                int word = ((bnw * 64 + ks) * 32 + fl) * 8 + bnt * 2 + reg;
                __stcg(&d_Tp_hi[word], pack_hi(v0, v1));
                __stcg(&d_Tp_lo[word], pack_lo(v0, v1));
            }
        }

        gridbar(gen);   // T fragments complete for next step (barrier 2)
    }
}

// =================================================================================
extern "C" void kernel_launch(void* const* d_in, const int* in_sizes, int n_in,
                              void* d_out, int out_size) {
    (void)in_sizes; (void)n_in; (void)out_size;
    const float* x    = (const float*)d_in[0];
    const float* WihF = (const float*)d_in[1];
    const float* WhhF = (const float*)d_in[2];
    const float* bihF = (const float*)d_in[3];
    const float* bhhF = (const float*)d_in[4];
    const float* WihR = (const float*)d_in[5];
    const float* WhhR = (const float*)d_in[6];
    const float* bihR = (const float*)d_in[7];
    const float* bhhR = (const float*)d_in[8];
    const float* WaFw = (const float*)d_in[9];
    const float* WaFb = (const float*)d_in[10];
    const float* WaRw = (const float*)d_in[11];
    const float* WaRb = (const float*)d_in[12];
    const float* Fw   = (const float*)d_in[13];
    const float* Fb   = (const float*)d_in[14];
    const float* Rw   = (const float*)d_in[15];
    const float* Rb   = (const float*)d_in[16];
    float* out = (float*)d_out;

    cudaFuncSetAttribute(phaseB_kernel,
                         cudaFuncAttributeMaxDynamicSharedMemorySize, 131072);

    pack_whh_kernel<<<16384, 256>>>(WhhF, WhhR);
    pack_wih_kernel<<<25600, 256>>>(WihF, WihR);
    pack_x_kernel<<<12800, 256>>>(x);
    pack_wa_kernel<<<448, 256>>>(WaFw, WaRw);
    phaseA_mma_kernel<<<dim3(256, 64), 256>>>(bihF, bhhF, bihR, bhhR);
    phaseB_kernel<<<NBLK, 512, 131072>>>(WaFb, WaRb, Fw, Fb, Rw, Rb, out);
}

// round 17
// speedup vs baseline: 1.0746x; 1.0370x over previous
#include <cuda_runtime.h>
#include <cuda_bf16.h>
#include <cstdint>
#include <math.h>

#define Bsz  64
#define Ssz  256
#define INP  400
#define Hsz  1024
#define H4   4096
#define Gsz  8192
#define NS   150
#define NR   50
#define NBLK 128

// ------------------------------- device scratch ---------------------------------
static __device__ float    d_Xg[(size_t)Ssz * Gsz * Bsz];   // [s][col(8192)][b]
static __device__ uint32_t d_Wp_hi[4194304];   // Whh A-frags [blk128][ks64][mw4][lane][4]
static __device__ uint32_t d_Wp_lo[4194304];
static __device__ uint32_t d_Tp_hi[2 * 32768]; // T B-frags, DOUBLE-BUFFERED by step parity
static __device__ uint32_t d_Tp_lo[2 * 32768];
static __device__ uint32_t d_WIp_hi[6553600];  // Wih A-frags [ct64][ks25][mw8][lane][4]
static __device__ uint32_t d_WIp_lo[6553600];
static __device__ uint32_t d_XIp_hi[3276800];  // x B-frags [s256][ks25][lane][16]
static __device__ uint32_t d_XIp_lo[3276800];
static __device__ uint32_t d_WAp_hi[114688];   // Wa A-frags [mt14][ks64][lane][4]
static __device__ uint32_t d_WAp_lo[114688];
static __device__ uint32_t d_HFp_hi[65536];    // h B-frags [cell2][nw2][ks64][lane][8]
static __device__ uint32_t d_HFp_lo[65536];
static __device__ float    d_lgG[4 * 200 * 64];  // logit K-partials [khB4][row200][batch64]
static __device__ unsigned g_bar, g_gen;
static __device__ unsigned g_hdone, g_lgdone, g_tdone;   // monotonic dataflow counters

// ------------------------------- helpers -----------------------------------------
#define MMA16816(c, a0, a1, a2, a3, b0, b1) \
    asm volatile("mma.sync.aligned.m16n8k16.row.col.f32.bf16.bf16.f32 " \
        "{%0,%1,%2,%3}, {%4,%5,%6,%7}, {%8,%9}, {%0,%1,%2,%3};" \
        : "+f"((c)[0]), "+f"((c)[1]), "+f"((c)[2]), "+f"((c)[3]) \
        : "r"(a0), "r"(a1), "r"(a2), "r"(a3), "r"(b0), "r"(b1))

// full grid barrier (used ONCE, after init)
__device__ __forceinline__ void gridbar(unsigned& gen) {
    __syncthreads();
    if (threadIdx.x == 0) {
        __threadfence();
        if (atomicAdd(&g_bar, 1u) == NBLK - 1) {
            atomicExch(&g_bar, 0u);
            __threadfence();
            atomicAdd(&g_gen, 1u);
        } else {
            while (*(volatile unsigned*)&g_gen == gen) { }
        }
        __threadfence();
    }
    __syncthreads();
    gen++;
}

// counter signal: all block stores visible, then bump counter
__device__ __forceinline__ void sig(unsigned* ctr) {
    __syncthreads();
    if (threadIdx.x == 0) {
        __threadfence();
        atomicAdd(ctr, 1u);
    }
}
// counter wait (wrap-safe), acquire + IVALL
__device__ __forceinline__ void waitc(const unsigned* ctr, unsigned base, unsigned target) {
    if (threadIdx.x == 0) {
        while ((unsigned)(*(volatile const unsigned*)ctr - base) < target) { }
        __threadfence();
    }
    __syncthreads();
}

__device__ __forceinline__ uint32_t pack_hi(float v0, float v1) {
    __nv_bfloat16 h0 = __float2bfloat16(v0), h1 = __float2bfloat16(v1);
    return (uint32_t)__bfloat16_as_ushort(h0) | ((uint32_t)__bfloat16_as_ushort(h1) << 16);
}
__device__ __forceinline__ uint32_t pack_lo(float v0, float v1) {
    __nv_bfloat16 h0 = __float2bfloat16(v0), h1 = __float2bfloat16(v1);
    float r0 = v0 - __bfloat162float(h0), r1 = v1 - __bfloat162float(h1);
    __nv_bfloat16 l0 = __float2bfloat16(r0), l1 = __float2bfloat16(r1);
    return (uint32_t)__bfloat16_as_ushort(l0) | ((uint32_t)__bfloat16_as_ushort(l1) << 16);
}
__device__ __forceinline__ float sigmf(float v) {
    return __fdividef(1.f, 1.f + __expf(-v));
}
__device__ __forceinline__ float tanhfast(float v) {
    return __fdividef(2.f, 1.f + __expf(-2.f * v)) - 1.f;
}

// =================================================================================
// pack Whh -> A-fragments
// =================================================================================
__global__ void __launch_bounds__(256) pack_whh_kernel(
    const float* __restrict__ WhhF, const float* __restrict__ WhhR)
{
    unsigned idx = blockIdx.x * 256u + threadIdx.x;        // < 4194304
    int w = idx & 3, lane = (idx >> 2) & 31, mw = (idx >> 7) & 3;
    int ks = (idx >> 9) & 63, blk = idx >> 15;
    int g = lane >> 2, t = lane & 3;
    int lr = g + 8 * (w & 1);
    int u = ((blk & 63) << 4) + lr;
    int k = ks * 16 + t * 2 + 8 * (w >> 1);
    const float* W = (blk >> 6) ? WhhR : WhhF;
    float2 v = *reinterpret_cast<const float2*>(&W[((size_t)mw * Hsz + u) * Hsz + k]);
    d_Wp_hi[idx] = pack_hi(v.x, v.y);
    d_Wp_lo[idx] = pack_lo(v.x, v.y);
}

// =================================================================================
// pack Wih (cat) -> A-fragments
// =================================================================================
__global__ void __launch_bounds__(256) pack_wih_kernel(
    const float* __restrict__ WihF, const float* __restrict__ WihR)
{
    unsigned idx = blockIdx.x * 256u + threadIdx.x;        // < 6553600
    int w = idx & 3, lane = (idx >> 2) & 31, mw = (idx >> 7) & 7;
    unsigned rest = idx >> 10;
    int ks = rest % 25, ct = rest / 25;
    int g = lane >> 2, t = lane & 3;
    int lr = g + 8 * (w & 1);
    int col = ct * 128 + mw * 16 + lr;
    int k = ks * 16 + t * 2 + 8 * (w >> 1);
    const float* W = (col < H4) ? (WihF + (size_t)col * INP)
                                : (WihR + (size_t)(col - H4) * INP);
    float2 v = *reinterpret_cast<const float2*>(&W[k]);
    d_WIp_hi[idx] = pack_hi(v.x, v.y);
    d_WIp_lo[idx] = pack_lo(v.x, v.y);
}

// =================================================================================
// pack x -> B-fragments
// =================================================================================
__global__ void __launch_bounds__(256) pack_x_kernel(const float* __restrict__ x)
{
    unsigned idx = blockIdx.x * 256u + threadIdx.x;        // < 3276800
    int w16 = idx & 15, lane = (idx >> 4) & 31;
    unsigned rest = idx >> 9;
    int ks = rest % 25, s = rest / 25;
    int nt = w16 >> 1, reg = w16 & 1;
    int b = nt * 8 + (lane >> 2);
    int k = ks * 16 + reg * 8 + (lane & 3) * 2;
    float2 v = *reinterpret_cast<const float2*>(&x[((size_t)b * Ssz + s) * INP + k]);
    d_XIp_hi[idx] = pack_hi(v.x, v.y);
    d_XIp_lo[idx] = pack_lo(v.x, v.y);
}

// =================================================================================
// pack Wa (F rows -> mtiles 0..9; R rows -> mtiles 10..13)
// =================================================================================
__global__ void __launch_bounds__(256) pack_wa_kernel(
    const float* __restrict__ WaFw, const float* __restrict__ WaRw)
{
    unsigned idx = blockIdx.x * 256u + threadIdx.x;        // < 114688
    int w = idx & 3, lane = (idx >> 2) & 31, ks = (idx >> 7) & 63, mt = idx >> 13;
    int g = lane >> 2, t = lane & 3;
    int lr = g + 8 * (w & 1);
    int k = ks * 16 + t * 2 + 8 * (w >> 1);
    float2 v = make_float2(0.f, 0.f);
    if (mt < 10) {
        int r = mt * 16 + lr;
        if (r < NS) v = *reinterpret_cast<const float2*>(&WaFw[(size_t)r * Hsz + k]);
    } else {
        int r = (mt - 10) * 16 + lr;
        if (r < NR) v = *reinterpret_cast<const float2*>(&WaRw[(size_t)r * Hsz + k]);
    }
    d_WAp_hi[idx] = pack_hi(v.x, v.y);
    d_WAp_lo[idx] = pack_lo(v.x, v.y);
}

// =================================================================================
// Phase A via HMMA bf16x3 (proven)
// =================================================================================
__global__ void __launch_bounds__(256, 2) phaseA_mma_kernel(
    const float* __restrict__ bihF, const float* __restrict__ bhhF,
    const float* __restrict__ bihR, const float* __restrict__ bhhR)
{
    const int s = blockIdx.x, ct = blockIdx.y;
    const int tid = threadIdx.x, wid = tid >> 5, lane = tid & 31;
    const int g = lane >> 2, t = lane & 3;

    float acc[8][4];
#pragma unroll
    for (int n = 0; n < 8; ++n)
#pragma unroll
        for (int i = 0; i < 4; ++i) acc[n][i] = 0.f;

    const uint4* pAh = (const uint4*)d_WIp_hi + ((size_t)(ct * 25) * 8 + wid) * 32 + lane;
    const uint4* pAl = (const uint4*)d_WIp_lo + ((size_t)(ct * 25) * 8 + wid) * 32 + lane;
    const uint4* pBh = (const uint4*)d_XIp_hi + ((size_t)(s * 25) * 32 + lane) * 4;
    const uint4* pBl = (const uint4*)d_XIp_lo + ((size_t)(s * 25) * 32 + lane) * 4;

    for (int ks = 0; ks < 25; ++ks) {
        uint32_t ah[4], al[4], bh[16], bl[16];
        *(uint4*)&ah[0] = __ldg(pAh);
        *(uint4*)&al[0] = __ldg(pAl);
#pragma unroll
        for (int j = 0; j < 4; ++j) {
            *(uint4*)&bh[4 * j] = __ldg(pBh + j);
            *(uint4*)&bl[4 * j] = __ldg(pBl + j);
        }
        pAh += 256; pAl += 256; pBh += 128; pBl += 128;
#pragma unroll
        for (int nt = 0; nt < 8; ++nt)
            MMA16816(acc[nt], ah[0], ah[1], ah[2], ah[3], bh[nt * 2], bh[nt * 2 + 1]);
#pragma unroll
        for (int nt = 0; nt < 8; ++nt)
            MMA16816(acc[nt], ah[0], ah[1], ah[2], ah[3], bl[nt * 2], bl[nt * 2 + 1]);
#pragma unroll
        for (int nt = 0; nt < 8; ++nt)
            MMA16816(acc[nt], al[0], al[1], al[2], al[3], bh[nt * 2], bh[nt * 2 + 1]);
    }

    const int cg0 = ct * 128 + wid * 16 + g, cg1 = cg0 + 8;
    float bs0 = (cg0 < H4) ? (bihF[cg0] + bhhF[cg0]) : (bihR[cg0 - H4] + bhhR[cg0 - H4]);
    float bs1 = (cg1 < H4) ? (bihF[cg1] + bhhF[cg1]) : (bihR[cg1 - H4] + bhhR[cg1 - H4]);
    float* base0 = &d_Xg[((size_t)s * Gsz + cg0) * Bsz];
    float* base1 = &d_Xg[((size_t)s * Gsz + cg1) * Bsz];
#pragma unroll
    for (int nt = 0; nt < 8; ++nt) {
        int n0 = nt * 8 + t * 2;
        *(float2*)&base0[n0] = make_float2(acc[nt][0] + bs0, acc[nt][1] + bs0);
        *(float2*)&base1[n0] = make_float2(acc[nt][2] + bs1, acc[nt][3] + bs1);
    }
}

// =================================================================================
// Phase B: counter-dataflow pipeline, ZERO full barriers in the step loop.
// T fragments double-buffered by step parity (kills the T WAR hazard).
// =================================================================================
__global__ void __launch_bounds__(512, 1) phaseB_kernel(
    const float* __restrict__ WaFb, const float* __restrict__ WaRb,
    const float* __restrict__ Fw,   const float* __restrict__ Fb,
    const float* __restrict__ Rw,   const float* __restrict__ Rb,
    float* __restrict__ out)
{
    extern __shared__ uint4 smWlo[];   // 8192 uint4 = 128KB (this block's W_lo frags)

    const int tid = threadIdx.x, blk = blockIdx.x;
    const int cell = blk >> 6, u0 = (blk & 63) << 4;
    const int wid = tid >> 5, lane = tid & 31;
    const int mw = wid & 3, nw = (wid >> 2) & 1, kh = wid >> 3;
    const int g = lane >> 2, t = lane & 3;

    __shared__ float gsm[64][68];
    __shared__ float lgsm[16][68];
    __shared__ float lg[256];
    __shared__ float itm[64];
    __shared__ unsigned s_gen, s_hb, s_lb, s_tb;

    for (int i = tid; i < 8192; i += 512)
        smWlo[i] = ((const uint4*)d_Wp_lo)[(size_t)blk * 8192 + i];

    {
        unsigned gi = blk * 512u + tid;        // 65536 threads == 2*32768 words
        __stcg(&d_Tp_hi[gi], 0u);
        __stcg(&d_Tp_lo[gi], 0u);
    }
    if (tid == 0) {
        s_gen = atomicAdd(&g_gen, 0u);
        s_hb  = atomicAdd(&g_hdone, 0u);
        s_lb  = atomicAdd(&g_lgdone, 0u);
        s_tb  = atomicAdd(&g_tdone, 0u);
    }
    __syncthreads();
    unsigned gen = s_gen;
    const unsigned hb = s_hb, lb = s_lb, tb = s_tb;
    gridbar(gen);   // publish T zero-init + counter bases before any signaling

    const uint4* pAh0 = (const uint4*)d_Wp_hi + (size_t)blk * 8192 + kh * 4096 + mw * 32 + lane;
    const uint4* sWl0 = smWlo + kh * 4096 + mw * 32 + lane;
    const int tpOff = nw * 4096 + kh * 2048 + lane * 2;

    const int gu = tid & 15, bq = tid >> 4;
    float cst[2] = {0.f, 0.f};

    float* outAF = out + (size_t)Bsz * Ssz * Hsz;
    float* outAR = outAF + (size_t)Bsz * Ssz * NS;

    for (int s = 0; s < Ssz; ++s) {
        // ---- wait: T(s) fragments ready (64 attention producers of step s-1) ----
        waitc(&g_tdone, tb, 64u * (unsigned)s);

        // ---- prefetch Xg gate slice ---------------------------------------------
        float2 xg[4];
#pragma unroll
        for (int gate = 0; gate < 4; ++gate) {
            size_t col = (size_t)cell * H4 + (size_t)gate * Hsz + u0 + gu;
            xg[gate] = *reinterpret_cast<const float2*>(
                &d_Xg[((size_t)s * Gsz + col) * Bsz + bq * 2]);
        }

        // ---- recurrent GEMM (bf16x3 HMMA; T buf parity s) ------------------------
        float acc[4][4];
#pragma unroll
        for (int n = 0; n < 4; ++n)
#pragma unroll
            for (int i = 0; i < 4; ++i) acc[n][i] = 0.f;

        const uint4* pAh = pAh0;
        const uint4* pBh = (const uint4*)d_Tp_hi + (s & 1) * 8192 + tpOff;
        const uint4* pBl = (const uint4*)d_Tp_lo + (s & 1) * 8192 + tpOff;
        uint4 cAh = __ldg(pAh);
        uint4 cB0 = pBh[0], cB1 = pBh[1];
        uint4 cB2 = pBl[0], cB3 = pBl[1];

#pragma unroll 4
        for (int ks = 0; ks < 32; ++ks) {
            uint4 nAh, nB0, nB1, nB2, nB3;
            if (ks < 31) {
                pAh += 128; pBh += 64; pBl += 64;
                nAh = __ldg(pAh);
                nB0 = pBh[0]; nB1 = pBh[1];
                nB2 = pBl[0]; nB3 = pBl[1];
            }
            uint4 cAl = sWl0[ks * 128];
            MMA16816(acc[0], cAh.x, cAh.y, cAh.z, cAh.w, cB0.x, cB0.y);
            MMA16816(acc[1], cAh.x, cAh.y, cAh.z, cAh.w, cB0.z, cB0.w);
            MMA16816(acc[2], cAh.x, cAh.y, cAh.z, cAh.w, cB1.x, cB1.y);
            MMA16816(acc[3], cAh.x, cAh.y, cAh.z, cAh.w, cB1.z, cB1.w);
            MMA16816(acc[0], cAh.x, cAh.y, cAh.z, cAh.w, cB2.x, cB2.y);
            MMA16816(acc[1], cAh.x, cAh.y, cAh.z, cAh.w, cB2.z, cB2.w);
            MMA16816(acc[2], cAh.x, cAh.y, cAh.z, cAh.w, cB3.x, cB3.y);
            MMA16816(acc[3], cAh.x, cAh.y, cAh.z, cAh.w, cB3.z, cB3.w);
            MMA16816(acc[0], cAl.x, cAl.y, cAl.z, cAl.w, cB0.x, cB0.y);
            MMA16816(acc[1], cAl.x, cAl.y, cAl.z, cAl.w, cB0.z, cB0.w);
            MMA16816(acc[2], cAl.x, cAl.y, cAl.z, cAl.w, cB1.x, cB1.y);
            MMA16816(acc[3], cAl.x, cAl.y, cAl.z, cAl.w, cB1.z, cB1.w);
            cAh = nAh; cB0 = nB0; cB1 = nB1; cB2 = nB2; cB3 = nB3;
        }

        if (kh == 1) {
#pragma unroll
            for (int nt = 0; nt < 4; ++nt) {
                int col = nw * 32 + nt * 8 + t * 2;
                float* r0 = &gsm[mw * 16 + g][col];
                r0[0] = acc[nt][0]; r0[1] = acc[nt][1];
                float* r1 = &gsm[mw * 16 + g + 8][col];
                r1[0] = acc[nt][2]; r1[1] = acc[nt][3];
            }
        }
        __syncthreads();
        if (kh == 0) {
#pragma unroll
            for (int nt = 0; nt < 4; ++nt) {
                int col = nw * 32 + nt * 8 + t * 2;
                float* r0 = &gsm[mw * 16 + g][col];
                r0[0] += acc[nt][0]; r0[1] += acc[nt][1];
                float* r1 = &gsm[mw * 16 + g + 8][col];
                r1[0] += acc[nt][2]; r1[1] += acc[nt][3];
            }
        }
        __syncthreads();

        // ---- gates -> h, packed directly as B-fragments --------------------------
        {
            float hv[2];
#pragma unroll
            for (int i = 0; i < 2; ++i) {
                int b = bq * 2 + i;
                float iv = gsm[      gu][b] + (i ? xg[0].y : xg[0].x);
                float fv = gsm[16 + gu][b] + (i ? xg[1].y : xg[1].x);
                float gv = gsm[32 + gu][b] + (i ? xg[2].y : xg[2].x);
                float ov = gsm[48 + gu][b] + (i ? xg[3].y : xg[3].x);
                float c2 = sigmf(fv) * cst[i] + sigmf(iv) * tanhfast(gv);
                cst[i] = c2;
                hv[i] = sigmf(ov) * tanhfast(c2);
            }
            float q0 = __shfl_xor_sync(0xffffffffu, hv[0], 1);
            float q1 = __shfl_xor_sync(0xffffffffu, hv[1], 1);
            if (!(gu & 1)) {
                int k = u0 + gu;
                int ks = k >> 4, reg = (k >> 3) & 1, tq = (k >> 1) & 3;
#pragma unroll
                for (int e = 0; e < 2; ++e) {
                    int n = bq * 2 + e;
                    float va = e ? hv[1] : hv[0];
                    float vb = e ? q1 : q0;
                    int nw2 = n >> 5, nt3 = (n >> 3) & 3;
                    int lane_t = (n & 7) * 4 + tq;
                    size_t widx = ((((size_t)cell * 2 + nw2) * 64 + ks) * 32 + lane_t) * 8
                                  + nt3 * 2 + reg;
                    __stcg(&d_HFp_hi[widx], pack_hi(va, vb));
                    __stcg(&d_HFp_lo[widx], pack_lo(va, vb));
                }
            }
        }

        sig(&g_hdone);   // h fragments published

        // ---- logits GEMM: 56 blocks, wait for all 128 h producers ---------------
        if (blk < 56) {
            waitc(&g_hdone, hb, 128u * (unsigned)(s + 1));

            const int mt = blk >> 2, khB = blk & 3;
            const int cellL = (mt < 10) ? 0 : 1;
            const int ntL = wid & 7, khL = wid >> 3;
            float la[4] = {0.f, 0.f, 0.f, 0.f};
            const uint32_t* A_h = d_WAp_hi + (size_t)mt * 8192;
            const uint32_t* A_l = d_WAp_lo + (size_t)mt * 8192;
            const uint32_t* B_h = d_HFp_hi + ((size_t)(cellL * 2 + (ntL >> 2))) * 16384;
            const uint32_t* B_l = d_HFp_lo + ((size_t)(cellL * 2 + (ntL >> 2))) * 16384;
            const int boff = (ntL & 3) * 2;
            const int ksBeg = khB * 16 + khL * 8, ksEnd = ksBeg + 8;
            for (int ks = ksBeg; ks < ksEnd; ++ks) {
                uint4 ah = __ldg((const uint4*)(A_h + ((size_t)ks * 32 + lane) * 4));
                uint4 al = __ldg((const uint4*)(A_l + ((size_t)ks * 32 + lane) * 4));
                uint2 bh = __ldcg((const uint2*)(B_h + ((size_t)ks * 32 + lane) * 8 + boff));
                uint2 bl = __ldcg((const uint2*)(B_l + ((size_t)ks * 32 + lane) * 8 + boff));
                MMA16816(la, ah.x, ah.y, ah.z, ah.w, bh.x, bh.y);
                MMA16816(la, ah.x, ah.y, ah.z, ah.w, bl.x, bl.y);
                MMA16816(la, al.x, al.y, al.z, al.w, bh.x, bh.y);
            }
            if (khL == 1) {
                int col = ntL * 8 + t * 2;
                lgsm[g][col] = la[0];     lgsm[g][col + 1] = la[1];
                lgsm[g + 8][col] = la[2]; lgsm[g + 8][col + 1] = la[3];
            }
            __syncthreads();
            if (khL == 0) {
                int col = ntL * 8 + t * 2;
                lgsm[g][col] += la[0];     lgsm[g][col + 1] += la[1];
                lgsm[g + 8][col] += la[2]; lgsm[g + 8][col + 1] += la[3];
            }
            __syncthreads();
#pragma unroll
            for (int e = 0; e < 2; ++e) {
                int idx = tid * 2 + e;
                int rl = idx >> 6, n = idx & 63;
                int rlg = (mt < 10) ? mt * 16 + rl : (mt - 10) * 16 + rl;
                bool valid = (mt < 10) ? (rlg < NS) : (rlg < NR);
                if (valid) {
                    int rg = (mt < 10) ? rlg : NS + rlg;
                    __stcg(&d_lgG[khB * 12800 + rg * 64 + n], lgsm[rl][n]);
                }
            }
            sig(&g_lgdone);   // logit partials published
        }

        // ---- attention: blocks 0..63, wait for all 56 logits producers ----------
        if (blk < Bsz) {
            waitc(&g_lgdone, lb, 56u * (unsigned)(s + 1));

            const int b = blk;
            if (tid < NS + NR)
                lg[tid] = __ldcg(&d_lgG[tid * 64 + b])
                          + __ldcg(&d_lgG[12800 + tid * 64 + b])
                          + __ldcg(&d_lgG[25600 + tid * 64 + b])
                          + __ldcg(&d_lgG[38400 + tid * 64 + b])
                          + ((tid < NS) ? __ldg(&WaFb[tid]) : __ldg(&WaRb[tid - NS]));
            __syncthreads();

            if (wid == 0) {
                float m = -1e30f;
                for (int n = lane; n < NS; n += 32) m = fmaxf(m, lg[n]);
#pragma unroll
                for (int off = 16; off; off >>= 1) m = fmaxf(m, __shfl_xor_sync(0xffffffffu, m, off));
                float ssum = 0.f;
                for (int n = lane; n < NS; n += 32) { float e = __expf(lg[n] - m); lg[n] = e; ssum += e; }
#pragma unroll
                for (int off = 16; off; off >>= 1) ssum += __shfl_xor_sync(0xffffffffu, ssum, off);
                float inv = 1.f / ssum;
                for (int n = lane; n < NS; n += 32) {
                    float a = lg[n] * inv; lg[n] = a;
                    outAF[((size_t)b * Ssz + s) * NS + n] = a;
                }
            } else if (wid == 1) {
                float m = -1e30f;
                for (int n = lane; n < NR; n += 32) m = fmaxf(m, lg[NS + n]);
#pragma unroll
                for (int off = 16; off; off >>= 1) m = fmaxf(m, __shfl_xor_sync(0xffffffffu, m, off));
                float ssum = 0.f;
                for (int n = lane; n < NR; n += 32) { float e = __expf(lg[NS + n] - m); lg[NS + n] = e; ssum += e; }
#pragma unroll
                for (int off = 16; off; off >>= 1) ssum += __shfl_xor_sync(0xffffffffu, ssum, off);
                float inv = 1.f / ssum;
                for (int n = lane; n < NR; n += 32) {
                    float a = lg[NS + n] * inv; lg[NS + n] = a;
                    outAR[((size_t)b * Ssz + s) * NR + n] = a;
                }
            }
            __syncthreads();

            if (tid < 32) {
                float sum = Fb[tid];
                for (int n = 0; n < NS; ++n) sum = fmaf(lg[n], __ldg(&Fw[tid * NS + n]), sum);
                itm[tid] = sum;
            } else if (tid < 64) {
                int d = tid - 32;
                float sum = Rb[d];
                for (int n = 0; n < NR; ++n) sum = fmaf(lg[NS + n], __ldg(&Rw[d * NR + n]), sum);
                itm[32 + d] = sum;
            }
            __syncthreads();

            // T row b -> main output + bf16 hi/lo B-fragments into buf parity (s+1)
            {
                const int pb = ((s + 1) & 1) * 32768;
                const int bnw = b >> 5, bnt = (b >> 3) & 3, bn = b & 7;
                int idx = tid;
                int ks = idx >> 3, q = idx & 3, reg = (idx >> 2) & 1;
                int k0 = ks * 16 + reg * 8 + q * 2;
                float v0 = itm[k0 >> 5] * itm[32 + (k0 & 31)];
                float v1 = itm[(k0 + 1) >> 5] * itm[32 + ((k0 + 1) & 31)];
                out[((size_t)b * Ssz + s) * Hsz + k0]     = v0;
                out[((size_t)b * Ssz + s) * Hsz + k0 + 1] = v1;
                int fl = bn * 4 + q;
                int word = ((bnw * 64 + ks) * 32 + fl) * 8 + bnt * 2 + reg;
                __stcg(&d_Tp_hi[pb + word], pack_hi(v0, v1));
                __stcg(&d_Tp_lo[pb + word], pack_lo(v0, v1));
            }
            sig(&g_tdone);   // T(s+1) published
        }
    }
}

// =================================================================================
extern "C" void kernel_launch(void* const* d_in, const int* in_sizes, int n_in,
                              void* d_out, int out_size) {
    (void)in_sizes; (void)n_in; (void)out_size;
    const float* x    = (const float*)d_in[0];
    const float* WihF = (const float*)d_in[1];
    const float* WhhF = (const float*)d_in[2];
    const float* bihF = (const float*)d_in[3];
    const float* bhhF = (const float*)d_in[4];
    const float* WihR = (const float*)d_in[5];
    const float* WhhR = (const float*)d_in[6];
    const float* bihR = (const float*)d_in[7];
    const float* bhhR = (const float*)d_in[8];
    const float* WaFw = (const float*)d_in[9];
    const float* WaFb = (const float*)d_in[10];
    const float* WaRw = (const float*)d_in[11];
    const float* WaRb = (const float*)d_in[12];
    const float* Fw   = (const float*)d_in[13];
    const float* Fb   = (const float*)d_in[14];
    const float* Rw   = (const float*)d_in[15];
    const float* Rb   = (const float*)d_in[16];
    float* out = (float*)d_out;

    cudaFuncSetAttribute(phaseB_kernel,
                         cudaFuncAttributeMaxDynamicSharedMemorySize, 131072);

    pack_whh_kernel<<<16384, 256>>>(WhhF, WhhR);
    pack_wih_kernel<<<25600, 256>>>(WihF, WihR);
    pack_x_kernel<<<12800, 256>>>(x);
    pack_wa_kernel<<<448, 256>>>(WaFw, WaRw);
    phaseA_mma_kernel<<<dim3(256, 64), 256>>>(bihF, bhhF, bihR, bhhR);
    phaseB_kernel<<<NBLK, 512, 131072>>>(WaFb, WaRb, Fw, Fb, Rw, Rb, out);
}